// round 2
// baseline (speedup 1.0000x reference)
#include <cuda_runtime.h>

#define P_CONST 5.0f
#define A_CONST 10.0f
#define MAX_CLAUSES 1000000

// Scratch: interleaved (numerator, denominator) per clause + loss accumulator.
__device__ float2 g_acc[MAX_CLAUSES];
__device__ double g_loss;

// ---------------------------------------------------------------------------
// Kernel 1: zero the accumulators
// ---------------------------------------------------------------------------
__global__ void zero_kernel(int C) {
    int stride = gridDim.x * blockDim.x;
    for (int i = blockIdx.x * blockDim.x + threadIdx.x; i < C; i += stride) {
        g_acc[i] = make_float2(0.0f, 0.0f);
    }
    if (blockIdx.x == 0 && threadIdx.x == 0) g_loss = 0.0;
}

// ---------------------------------------------------------------------------
// Kernel 2: edge scatter. Each thread handles one positive and one negative
// edge (same lane index i in [0, E)).
//   pos: lit = x[v],      w = exp(P * lit)
//   neg: lit = 1 - x[v],  w = exp(P * lit)
//   acc[c] += (lit*w, w)
// ---------------------------------------------------------------------------
__global__ void __launch_bounds__(256) edge_kernel(
    const float* __restrict__ x,
    const int* __restrict__ adj_pos,   // [2, E]: row 0 = clause, row 1 = var
    const int* __restrict__ adj_neg,   // [2, E]
    int E)
{
    int i = blockIdx.x * blockDim.x + threadIdx.x;
    if (i >= E) return;

    // positive polarity edge
    {
        int c = adj_pos[i];
        int v = adj_pos[E + i];
        float lit = __ldg(x + v);
        float w = __expf(P_CONST * lit);
        atomicAdd(&g_acc[c].x, lit * w);
        atomicAdd(&g_acc[c].y, w);
    }
    // negative polarity edge
    {
        int c = adj_neg[i];
        int v = adj_neg[E + i];
        float lit = 1.0f - __ldg(x + v);
        float w = __expf(P_CONST * lit);
        atomicAdd(&g_acc[c].x, lit * w);
        atomicAdd(&g_acc[c].y, w);
    }
}

// ---------------------------------------------------------------------------
// Kernel 3: per-clause sigmoid + squared error, block-reduced into g_loss.
// ---------------------------------------------------------------------------
__global__ void __launch_bounds__(256) loss_kernel(
    const float* __restrict__ clause_count, int C)
{
    float local = 0.0f;
    int stride = gridDim.x * blockDim.x;
    for (int i = blockIdx.x * blockDim.x + threadIdx.x; i < C; i += stride) {
        float2 a = g_acc[i];
        float mean = a.x / a.y;                      // den > 0 (every clause non-empty)
        float z = A_CONST * (mean - 0.5f);
        float sm = 1.0f / (1.0f + __expf(-z));       // sigmoid
        float d = sm - clause_count[i];
        local += d * d;
    }

    #pragma unroll
    for (int off = 16; off > 0; off >>= 1)
        local += __shfl_down_sync(0xffffffffu, local, off);

    __shared__ float warp_sums[8];
    int lane = threadIdx.x & 31;
    int wid = threadIdx.x >> 5;
    if (lane == 0) warp_sums[wid] = local;
    __syncthreads();

    if (wid == 0) {
        float s = (lane < (blockDim.x >> 5)) ? warp_sums[lane] : 0.0f;
        #pragma unroll
        for (int off = 4; off > 0; off >>= 1)
            s += __shfl_down_sync(0xffffffffu, s, off);
        if (lane == 0) atomicAdd(&g_loss, (double)s);
    }
}

// ---------------------------------------------------------------------------
// Kernel 4: finalize mean
// ---------------------------------------------------------------------------
__global__ void finalize_kernel(float* out, double invC) {
    *out = (float)(g_loss * invC);
}

// ---------------------------------------------------------------------------
// Launch
// Inputs (metadata order): xv f32 [V], adj_pos i32 [2*E], adj_neg i32 [2*E],
//                          clause_count f32 [C]. Output: f32 scalar loss.
// ---------------------------------------------------------------------------
extern "C" void kernel_launch(void* const* d_in, const int* in_sizes, int n_in,
                              void* d_out, int out_size)
{
    const float* xv = (const float*)d_in[0];
    const int*   ap = (const int*)d_in[1];
    const int*   an = (const int*)d_in[2];
    const float* cc = (const float*)d_in[3];
    float* out = (float*)d_out;

    int E = in_sizes[1] / 2;   // 3,000,000
    int C = in_sizes[3];       // 1,000,000

    const int T = 256;
    zero_kernel<<<2048, T>>>(C);

    int edge_blocks = (E + T - 1) / T;
    edge_kernel<<<edge_blocks, T>>>(xv, ap, an, E);

    loss_kernel<<<2048, T>>>(cc, C);

    finalize_kernel<<<1, 1>>>(out, 1.0 / (double)C);
}

// round 3
// speedup vs baseline: 1.3683x; 1.3683x over previous
#include <cuda_runtime.h>

#define P_CONST 5.0f
#define A_CONST 10.0f
#define MAX_CLAUSES 1000000

// Scratch: interleaved (numerator, denominator) per clause + loss accumulator.
__device__ float2 g_acc[MAX_CLAUSES];
__device__ double g_loss;
__device__ unsigned int g_done;   // last-block-done counter for loss kernel

// ---------------------------------------------------------------------------
// Kernel 1: zero accumulators (vectorized float4 = 2 clauses per store)
// ---------------------------------------------------------------------------
__global__ void zero_kernel(int C) {
    int stride = gridDim.x * blockDim.x;
    float4* p = reinterpret_cast<float4*>(g_acc);
    int n4 = C / 2;   // C is even (1M)
    for (int i = blockIdx.x * blockDim.x + threadIdx.x; i < n4; i += stride) {
        p[i] = make_float4(0.f, 0.f, 0.f, 0.f);
    }
    if (blockIdx.x == 0 && threadIdx.x == 0) { g_loss = 0.0; g_done = 0u; }
}

// ---------------------------------------------------------------------------
// Kernel 2: edge scatter, 4 pos + 4 neg edges per thread.
// Index rows loaded as int4; (lit*w, w) accumulated with ONE float2 atomic.
// ---------------------------------------------------------------------------
__device__ __forceinline__ void scatter_edge(const float* __restrict__ x,
                                             int c, int v, bool neg)
{
    float lit = __ldg(x + v);
    if (neg) lit = 1.0f - lit;
    float w = __expf(P_CONST * lit);
#if __CUDA_ARCH__ >= 900
    atomicAdd(reinterpret_cast<float2*>(&g_acc[c]), make_float2(lit * w, w));
#else
    atomicAdd(&g_acc[c].x, lit * w);
    atomicAdd(&g_acc[c].y, w);
#endif
}

__global__ void __launch_bounds__(256) edge_kernel(
    const float* __restrict__ x,
    const int* __restrict__ adj_pos,   // [2, E]: row 0 = clause, row 1 = var
    const int* __restrict__ adj_neg,   // [2, E]
    int E4)                            // E/4
{
    int i = blockIdx.x * blockDim.x + threadIdx.x;
    if (i >= E4) return;

    const int E = E4 * 4;
    const int4* cp4 = reinterpret_cast<const int4*>(adj_pos);
    const int4* vp4 = reinterpret_cast<const int4*>(adj_pos + E);
    const int4* cn4 = reinterpret_cast<const int4*>(adj_neg);
    const int4* vn4 = reinterpret_cast<const int4*>(adj_neg + E);

    int4 cp = cp4[i];
    int4 vp = vp4[i];
    int4 cn = cn4[i];
    int4 vn = vn4[i];

    scatter_edge(x, cp.x, vp.x, false);
    scatter_edge(x, cp.y, vp.y, false);
    scatter_edge(x, cp.z, vp.z, false);
    scatter_edge(x, cp.w, vp.w, false);

    scatter_edge(x, cn.x, vn.x, true);
    scatter_edge(x, cn.y, vn.y, true);
    scatter_edge(x, cn.z, vn.z, true);
    scatter_edge(x, cn.w, vn.w, true);
}

// ---------------------------------------------------------------------------
// Kernel 3: per-clause sigmoid + squared error, block-reduced into g_loss,
// with last-block finalize (writes mean to out).
// ---------------------------------------------------------------------------
__global__ void __launch_bounds__(256) loss_kernel(
    const float* __restrict__ clause_count, int C, float* out, float invC)
{
    float local = 0.0f;
    int stride = gridDim.x * blockDim.x;
    for (int i = blockIdx.x * blockDim.x + threadIdx.x; i < C; i += stride) {
        float2 a = g_acc[i];
        float mean = a.x / a.y;                      // den > 0 (every clause non-empty)
        float z = A_CONST * (mean - 0.5f);
        float sm = 1.0f / (1.0f + __expf(-z));       // sigmoid
        float d = sm - clause_count[i];
        local += d * d;
    }

    #pragma unroll
    for (int off = 16; off > 0; off >>= 1)
        local += __shfl_down_sync(0xffffffffu, local, off);

    __shared__ float warp_sums[8];
    __shared__ bool is_last;
    int lane = threadIdx.x & 31;
    int wid = threadIdx.x >> 5;
    if (lane == 0) warp_sums[wid] = local;
    __syncthreads();

    if (wid == 0) {
        float s = (lane < (blockDim.x >> 5)) ? warp_sums[lane] : 0.0f;
        #pragma unroll
        for (int off = 4; off > 0; off >>= 1)
            s += __shfl_down_sync(0xffffffffu, s, off);
        if (lane == 0) {
            atomicAdd(&g_loss, (double)s);
            __threadfence();
            unsigned int ticket = atomicAdd(&g_done, 1u);
            is_last = (ticket == gridDim.x - 1);
        }
    }
    __syncthreads();

    if (is_last && threadIdx.x == 0) {
        *out = (float)g_loss * invC;
    }
}

// ---------------------------------------------------------------------------
// Launch
// Inputs (metadata order): xv f32 [V], adj_pos i32 [2*E], adj_neg i32 [2*E],
//                          clause_count f32 [C]. Output: f32 scalar loss.
// ---------------------------------------------------------------------------
extern "C" void kernel_launch(void* const* d_in, const int* in_sizes, int n_in,
                              void* d_out, int out_size)
{
    const float* xv = (const float*)d_in[0];
    const int*   ap = (const int*)d_in[1];
    const int*   an = (const int*)d_in[2];
    const float* cc = (const float*)d_in[3];
    float* out = (float*)d_out;

    int E = in_sizes[1] / 2;   // 3,000,000
    int C = in_sizes[3];       // 1,000,000
    int E4 = E / 4;            // E divisible by 4

    const int T = 256;
    zero_kernel<<<2048, T>>>(C);

    int edge_blocks = (E4 + T - 1) / T;
    edge_kernel<<<edge_blocks, T>>>(xv, ap, an, E4);

    loss_kernel<<<2048, T>>>(cc, C, out, 1.0f / (float)C);
}